// round 2
// baseline (speedup 1.0000x reference)
#include <cuda_runtime.h>
#include <cuda_bf16.h>

// Problem constants
#define B_MOLS 256
#define M_ATOMS 48
#define EDGES_PER_MOL (M_ATOMS * (M_ATOMS - 1))   // 2256
#define E_TOTAL (B_MOLS * EDGES_PER_MOL)          // 577536
#define N_ATOMS (B_MOLS * M_ATOMS)                // 12288
#define K_RBF 32
#define HS 128
#define NSH 25
#define FEAT_W 57                                  // 32 RBF + 25 SH

// Output layout (flattened reference tuple, float32)
#define OFF_FEAT 0ULL
#define OFF_EMB  ((size_t)E_TOTAL * FEAT_W)                    // 32919552
#define OFF_EI   (OFF_EMB + (size_t)N_ATOMS * HS)              // 34492416
#define OFF_TR   (OFF_EI + 2ULL * E_TOTAL)                     // 35647488

#define EPB 128
#define EDGE_BLOCKS (E_TOTAL / EPB)                            // 4512
#define EMB_F4 (N_ATOMS * HS / 4)                              // 393216
#define EMB_BLOCKS (EMB_F4 / EPB)                              // 3072

// ---------------------------------------------------------------------------
// Single fused kernel. Blocks [0, EDGE_BLOCKS) compute edge features + index
// arrays; blocks [EDGE_BLOCKS, EDGE_BLOCKS+EMB_BLOCKS) do the embedding
// gather. Tables (log-binomials, SH coefficients) are built per edge-block in
// shared memory by the first 57 threads — cheap float work, hidden in startup.
// ---------------------------------------------------------------------------
__global__ __launch_bounds__(EPB) void fused_kernel(
    const float* __restrict__ pos,
    const float* __restrict__ alpha,
    const int*   __restrict__ an,
    const float* __restrict__ table,
    float* __restrict__ out)
{
    // ---------------- embedding-gather blocks ----------------
    if (blockIdx.x >= EDGE_BLOCKS) {
        const int i = (blockIdx.x - EDGE_BLOCKS) * EPB + threadIdx.x; // < EMB_F4
        const int n = i >> 5;            // 32 float4 per node (HS=128)
        const int h = i & 31;
        const int a = __ldg(&an[n]);
        const float4 v = ((const float4*)table)[a * 32 + h];
        ((float4*)(out + OFF_EMB))[i] = v;
        return;
    }

    // ---------------- edge blocks ----------------
    __shared__ float sfeat[EPB * FEAT_W];   // 29184 B
    __shared__ float s_logbinom[K_RBF];
    __shared__ float s_shcoef[NSH];

    {
        const int t = threadIdx.x;
        if (t < K_RBF) {
            // ln C(31, t)
            s_logbinom[t] = lgammaf(32.0f) - lgammaf((float)t + 1.0f)
                          - lgammaf(32.0f - (float)t);
        } else if (t < K_RBF + NSH) {
            const int j = t - K_RBF;          // j = l*l + l + m
            int l = 0;
            while ((l + 1) * (l + 1) <= j) l++;
            const int m = j - l * l - l;
            const int am = m < 0 ? -m : m;
            float fr = 1.0f;                  // (l-am)! / (l+am)!  (exact: ints < 2^24)
            for (int i = l - am + 1; i <= l + am; i++) fr /= (float)i;
            float c = sqrtf((float)(2 * l + 1) * fr);
            if (m != 0) c *= 1.41421356237309515f;
            s_shcoef[j] = c;
        }
    }
    __syncthreads();

    const int e0 = blockIdx.x * EPB;
    const int e  = e0 + threadIdx.x;

    // Decode edge -> (b, src s, dst d)
    const int b = e / EDGES_PER_MOL;
    const int t = e - b * EDGES_PER_MOL;
    const int s = t / (M_ATOMS - 1);
    const int k = t - s * (M_ATOMS - 1);
    const int d = k + (k >= s ? 1 : 0);
    const int dst = b * M_ATOMS + d;
    const int src = b * M_ATOMS + s;

    // Edge vector (pos: 147 KB, L2-resident; src row broadcast within warp)
    const float ex = pos[dst * 3 + 0] - pos[src * 3 + 0];
    const float ey = pos[dst * 3 + 1] - pos[src * 3 + 1];
    const float ez = pos[dst * 3 + 2] - pos[src * 3 + 2];
    float r = sqrtf(ex * ex + ey * ey + ez * ez);
    r = fmaxf(r, 1e-6f);
    const float inv_r = 1.0f / r;

    // --- RBF: exponential Bernstein x bump cutoff ---
    const float a  = 0.5f * alpha[0];
    const float xx = -a * r;
    const float lp = logf(-expm1f(xx));          // log(1 - e^{xx})
    const float rc  = r * (1.0f / 15.0f);
    const float den = fmaxf((1.0f - rc) * (1.0f + rc), 1e-9f);
    const float fcut = (rc < 1.0f) ? expf(-rc * rc / den) : 0.0f;

    float* row = &sfeat[threadIdx.x * FEAT_W];
    #pragma unroll
    for (int v = 0; v < K_RBF; v++) {
        float logb = s_logbinom[v] + (float)(K_RBF - 1 - v) * xx + (float)v * lp;
        row[v] = fcut * expf(logb);
    }

    // --- Real spherical harmonics (component-normalized, z-up), LMAX=4 ---
    const float x = ex * inv_r, y = ey * inv_r, z = ez * inv_r;

    const float C1 = x,               S1 = y;
    const float C2 = C1 * x - S1 * y, S2 = S1 * x + C1 * y;
    const float C3 = C2 * x - S2 * y, S3 = S2 * x + C2 * y;
    const float C4 = C3 * x - S3 * y, S4 = S3 * x + C3 * y;

    const float Q00 = 1.0f;
    const float Q10 = z;
    const float Q20 = (3.0f * z * Q10 - 1.0f * Q00) * 0.5f;
    const float Q30 = (5.0f * z * Q20 - 2.0f * Q10) * (1.0f / 3.0f);
    const float Q40 = (7.0f * z * Q30 - 3.0f * Q20) * 0.25f;
    const float Q11 = 1.0f;
    const float Q21 = 3.0f * z;
    const float Q31 = (5.0f * z * Q21 - 3.0f * Q11) * 0.5f;
    const float Q41 = (7.0f * z * Q31 - 4.0f * Q21) * (1.0f / 3.0f);
    const float Q22 = 3.0f;
    const float Q32 = 5.0f * z * Q22;
    const float Q42 = (7.0f * z * Q32 - 5.0f * Q22) * 0.5f;
    const float Q33 = 15.0f;
    const float Q43 = 7.0f * z * Q33;
    const float Q44 = 105.0f;

    float* sh = row + K_RBF;
    sh[0]  = s_shcoef[0];
    sh[1]  = s_shcoef[1]  * Q11 * S1;
    sh[2]  = s_shcoef[2]  * Q10;
    sh[3]  = s_shcoef[3]  * Q11 * C1;
    sh[4]  = s_shcoef[4]  * Q22 * S2;
    sh[5]  = s_shcoef[5]  * Q21 * S1;
    sh[6]  = s_shcoef[6]  * Q20;
    sh[7]  = s_shcoef[7]  * Q21 * C1;
    sh[8]  = s_shcoef[8]  * Q22 * C2;
    sh[9]  = s_shcoef[9]  * Q33 * S3;
    sh[10] = s_shcoef[10] * Q32 * S2;
    sh[11] = s_shcoef[11] * Q31 * S1;
    sh[12] = s_shcoef[12] * Q30;
    sh[13] = s_shcoef[13] * Q31 * C1;
    sh[14] = s_shcoef[14] * Q32 * C2;
    sh[15] = s_shcoef[15] * Q33 * C3;
    sh[16] = s_shcoef[16] * Q44 * S4;
    sh[17] = s_shcoef[17] * Q43 * S3;
    sh[18] = s_shcoef[18] * Q42 * S2;
    sh[19] = s_shcoef[19] * Q41 * S1;
    sh[20] = s_shcoef[20] * Q40;
    sh[21] = s_shcoef[21] * Q41 * C1;
    sh[22] = s_shcoef[22] * Q42 * C2;
    sh[23] = s_shcoef[23] * Q43 * C3;
    sh[24] = s_shcoef[24] * Q44 * C4;

    // --- edge_index + transpose_index (coalesced scalar stores) ---
    out[OFF_EI + e]           = (float)dst;
    out[OFF_EI + E_TOTAL + e] = (float)src;
    const int tr = b * EDGES_PER_MOL + d * (M_ATOMS - 1) + s - (d < s ? 1 : 0);
    out[OFF_TR + e] = (float)tr;

    __syncthreads();

    // --- Cooperative coalesced drain of feature rows (float4, STG.128) ---
    float4* __restrict__ dst4 = (float4*)(out + (size_t)e0 * FEAT_W);  // 29184B / block, 16B aligned
    const float4* __restrict__ src4 = (const float4*)sfeat;
    #pragma unroll
    for (int i = threadIdx.x; i < (EPB * FEAT_W) / 4; i += EPB) {
        dst4[i] = src4[i];
    }
}

extern "C" void kernel_launch(void* const* d_in, const int* in_sizes, int n_in,
                              void* d_out, int out_size) {
    const float* pos   = (const float*)d_in[0];
    const int*   an    = (const int*)d_in[1];
    const float* table = (const float*)d_in[2];
    const float* alpha = (const float*)d_in[3];
    float* out = (float*)d_out;

    fused_kernel<<<EDGE_BLOCKS + EMB_BLOCKS, EPB>>>(pos, alpha, an, table, out);
}

// round 4
// speedup vs baseline: 1.8687x; 1.8687x over previous
#include <cuda_runtime.h>
#include <cuda_bf16.h>

// Problem constants
#define B_MOLS 256
#define M_ATOMS 48
#define EDGES_PER_MOL (M_ATOMS * (M_ATOMS - 1))   // 2256
#define E_TOTAL (B_MOLS * EDGES_PER_MOL)          // 577536
#define N_ATOMS (B_MOLS * M_ATOMS)                // 12288
#define K_RBF 32
#define HS 128
#define NSH 25
#define FEAT_W 57                                  // 32 RBF + 25 SH

// Output layout (flattened reference tuple, float32)
#define OFF_FEAT 0ULL
#define OFF_EMB  ((size_t)E_TOTAL * FEAT_W)                    // 32919552
#define OFF_EI   (OFF_EMB + (size_t)N_ATOMS * HS)              // 34492416
#define OFF_TR   (OFF_EI + 2ULL * E_TOTAL)                     // 35647488

#define EPB 128
#define EDGE_BLOCKS (E_TOTAL / EPB)                            // 4512
#define EMB_F4 (N_ATOMS * HS / 4)                              // 393216
#define EMB_BLOCKS (EMB_F4 / EPB)                              // 3072

// ln C(31, v), v = 0..31 (exact binomials, logs to ~1e-7)
__constant__ float c_logbinom[K_RBF] = {
    0.0f,        3.4339872f,  6.1420374f,  8.4107209f,
    10.3566311f, 12.0430300f, 13.5093671f, 14.7823328f,
    15.8809451f, 16.8192147f, 17.6076721f, 18.2542992f,
    18.7651249f, 19.1446145f, 19.3959290f, 19.5210921f,
    19.5210921f, 19.3959290f, 19.1446145f, 18.7651249f,
    18.2542992f, 17.6076721f, 16.8192147f, 15.8809451f,
    14.7823328f, 13.5093671f, 12.0430300f, 10.3566311f,
    8.4107209f,  6.1420374f,  3.4339872f,  0.0f
};

// sqrt((2l+1)(l-|m|)!/(l+|m|)!) * (sqrt(2) if m!=0), j = l*l+l+m
__constant__ float c_shcoef[NSH] = {
    1.0f,
    1.7320508f, 1.7320508f, 1.7320508f,
    0.6454972f, 1.2909944f, 2.2360680f, 1.2909944f, 0.6454972f,
    0.1394333f, 0.3415650f, 1.0801234f, 2.6457513f, 1.0801234f, 0.3415650f, 0.1394333f,
    0.0211289f, 0.0597614f, 0.2236068f, 0.9486833f, 3.0f,
    0.9486833f, 0.2236068f, 0.0597614f, 0.0211289f
};

// ---------------------------------------------------------------------------
// Single fused kernel. Blocks [0, EDGE_BLOCKS) compute edge features + index
// arrays; remaining blocks do the embedding gather. No runtime table setup.
// ---------------------------------------------------------------------------
__global__ __launch_bounds__(EPB) void fused_kernel(
    const float* __restrict__ pos,
    const float* __restrict__ alpha,
    const int*   __restrict__ an,
    const float* __restrict__ table,
    float* __restrict__ out)
{
    // ---------------- embedding-gather blocks ----------------
    if (blockIdx.x >= EDGE_BLOCKS) {
        const int i = (blockIdx.x - EDGE_BLOCKS) * EPB + threadIdx.x; // < EMB_F4
        const int n = i >> 5;            // 32 float4 per node (HS=128)
        const int h = i & 31;
        const int a = __ldg(&an[n]);
        const float4 v = ((const float4*)table)[a * 32 + h];
        ((float4*)(out + OFF_EMB))[i] = v;
        return;
    }

    // ---------------- edge blocks ----------------
    __shared__ float sfeat[EPB * FEAT_W];   // 29184 B

    const int e0 = blockIdx.x * EPB;
    const int e  = e0 + threadIdx.x;

    // Decode edge -> (b, src s, dst d)
    const int b = e / EDGES_PER_MOL;
    const int t = e - b * EDGES_PER_MOL;
    const int s = t / (M_ATOMS - 1);
    const int k = t - s * (M_ATOMS - 1);
    const int d = k + (k >= s ? 1 : 0);
    const int dst = b * M_ATOMS + d;
    const int src = b * M_ATOMS + s;

    // Edge vector (pos: 147 KB, L1/L2-resident)
    const float ex = pos[dst * 3 + 0] - pos[src * 3 + 0];
    const float ey = pos[dst * 3 + 1] - pos[src * 3 + 1];
    const float ez = pos[dst * 3 + 2] - pos[src * 3 + 2];
    float r = sqrtf(ex * ex + ey * ey + ez * ez);
    r = fmaxf(r, 1e-6f);
    const float inv_r = 1.0f / r;

    // --- RBF: exponential Bernstein x bump cutoff ---
    const float a  = 0.5f * alpha[0];
    const float xx = -a * r;
    const float lp = __logf(-expm1f(xx));        // log(1 - e^{xx})
    const float rc  = r * (1.0f / 15.0f);
    const float den = fmaxf((1.0f - rc) * (1.0f + rc), 1e-9f);
    const float fcut = (rc < 1.0f) ? __expf(-rc * rc / den) : 0.0f;

    float* row = &sfeat[threadIdx.x * FEAT_W];
    #pragma unroll
    for (int v = 0; v < K_RBF; v++) {
        float logb = c_logbinom[v] + (float)(K_RBF - 1 - v) * xx + (float)v * lp;
        row[v] = fcut * __expf(logb);
    }

    // --- Real spherical harmonics (component-normalized, z-up), LMAX=4 ---
    const float x = ex * inv_r, y = ey * inv_r, z = ez * inv_r;

    const float C1 = x,               S1 = y;
    const float C2 = C1 * x - S1 * y, S2 = S1 * x + C1 * y;
    const float C3 = C2 * x - S2 * y, S3 = S2 * x + C2 * y;
    const float C4 = C3 * x - S3 * y, S4 = S3 * x + C3 * y;

    const float Q00 = 1.0f;
    const float Q10 = z;
    const float Q20 = (3.0f * z * Q10 - 1.0f * Q00) * 0.5f;
    const float Q30 = (5.0f * z * Q20 - 2.0f * Q10) * (1.0f / 3.0f);
    const float Q40 = (7.0f * z * Q30 - 3.0f * Q20) * 0.25f;
    const float Q11 = 1.0f;
    const float Q21 = 3.0f * z;
    const float Q31 = (5.0f * z * Q21 - 3.0f * Q11) * 0.5f;
    const float Q41 = (7.0f * z * Q31 - 4.0f * Q21) * (1.0f / 3.0f);
    const float Q22 = 3.0f;
    const float Q32 = 5.0f * z * Q22;
    const float Q42 = (7.0f * z * Q32 - 5.0f * Q22) * 0.5f;
    const float Q33 = 15.0f;
    const float Q43 = 7.0f * z * Q33;
    const float Q44 = 105.0f;

    float* sh = row + K_RBF;
    sh[0]  = c_shcoef[0];
    sh[1]  = c_shcoef[1]  * Q11 * S1;
    sh[2]  = c_shcoef[2]  * Q10;
    sh[3]  = c_shcoef[3]  * Q11 * C1;
    sh[4]  = c_shcoef[4]  * Q22 * S2;
    sh[5]  = c_shcoef[5]  * Q21 * S1;
    sh[6]  = c_shcoef[6]  * Q20;
    sh[7]  = c_shcoef[7]  * Q21 * C1;
    sh[8]  = c_shcoef[8]  * Q22 * C2;
    sh[9]  = c_shcoef[9]  * Q33 * S3;
    sh[10] = c_shcoef[10] * Q32 * S2;
    sh[11] = c_shcoef[11] * Q31 * S1;
    sh[12] = c_shcoef[12] * Q30;
    sh[13] = c_shcoef[13] * Q31 * C1;
    sh[14] = c_shcoef[14] * Q32 * C2;
    sh[15] = c_shcoef[15] * Q33 * C3;
    sh[16] = c_shcoef[16] * Q44 * S4;
    sh[17] = c_shcoef[17] * Q43 * S3;
    sh[18] = c_shcoef[18] * Q42 * S2;
    sh[19] = c_shcoef[19] * Q41 * S1;
    sh[20] = c_shcoef[20] * Q40;
    sh[21] = c_shcoef[21] * Q41 * C1;
    sh[22] = c_shcoef[22] * Q42 * C2;
    sh[23] = c_shcoef[23] * Q43 * C3;
    sh[24] = c_shcoef[24] * Q44 * C4;

    // --- edge_index + transpose_index (coalesced scalar stores) ---
    out[OFF_EI + e]           = (float)dst;
    out[OFF_EI + E_TOTAL + e] = (float)src;
    const int tr = b * EDGES_PER_MOL + d * (M_ATOMS - 1) + s - (d < s ? 1 : 0);
    out[OFF_TR + e] = (float)tr;

    __syncthreads();

    // --- Cooperative coalesced drain of feature rows (float4, STG.128) ---
    float4* __restrict__ dst4 = (float4*)(out + (size_t)e0 * FEAT_W);  // 29184B / block, 16B aligned
    const float4* __restrict__ src4 = (const float4*)sfeat;
    #pragma unroll
    for (int i = threadIdx.x; i < (EPB * FEAT_W) / 4; i += EPB) {
        dst4[i] = src4[i];
    }
}

extern "C" void kernel_launch(void* const* d_in, const int* in_sizes, int n_in,
                              void* d_out, int out_size) {
    const float* pos   = (const float*)d_in[0];
    const int*   an    = (const int*)d_in[1];
    const float* table = (const float*)d_in[2];
    const float* alpha = (const float*)d_in[3];
    float* out = (float*)d_out;

    fused_kernel<<<EDGE_BLOCKS + EMB_BLOCKS, EPB>>>(pos, alpha, an, table, out);
}

// round 5
// speedup vs baseline: 1.8729x; 1.0022x over previous
#include <cuda_runtime.h>
#include <cuda_bf16.h>
#include <cstdint>

// Problem constants
#define B_MOLS 256
#define M_ATOMS 48
#define EDGES_PER_MOL (M_ATOMS * (M_ATOMS - 1))   // 2256
#define E_TOTAL (B_MOLS * EDGES_PER_MOL)          // 577536
#define N_ATOMS (B_MOLS * M_ATOMS)                // 12288
#define K_RBF 32
#define HS 128
#define NSH 25
#define FEAT_W 57                                  // 32 RBF + 25 SH

// Output layout (flattened reference tuple, float32)
#define OFF_FEAT 0ULL
#define OFF_EMB  ((size_t)E_TOTAL * FEAT_W)                    // 32919552
#define OFF_EI   (OFF_EMB + (size_t)N_ATOMS * HS)              // 34492416
#define OFF_TR   (OFF_EI + 2ULL * E_TOTAL)                     // 35647488

#define EPB 192
#define EDGE_BLOCKS (E_TOTAL / EPB)                            // 3008
#define EMB_F4 (N_ATOMS * HS / 4)                              // 393216
#define EMB_BLOCKS (EMB_F4 / EPB)                              // 2048

// ln C(31, v), v = 0..31
__constant__ float c_logbinom[K_RBF] = {
    0.0f,        3.4339872f,  6.1420374f,  8.4107209f,
    10.3566311f, 12.0430300f, 13.5093671f, 14.7823328f,
    15.8809451f, 16.8192147f, 17.6076721f, 18.2542992f,
    18.7651249f, 19.1446145f, 19.3959290f, 19.5210921f,
    19.5210921f, 19.3959290f, 19.1446145f, 18.7651249f,
    18.2542992f, 17.6076721f, 16.8192147f, 15.8809451f,
    14.7823328f, 13.5093671f, 12.0430300f, 10.3566311f,
    8.4107209f,  6.1420374f,  3.4339872f,  0.0f
};

// sqrt((2l+1)(l-|m|)!/(l+|m|)!) * (sqrt(2) if m!=0), j = l*l+l+m
__constant__ float c_shcoef[NSH] = {
    1.0f,
    1.7320508f, 1.7320508f, 1.7320508f,
    0.6454972f, 1.2909944f, 2.2360680f, 1.2909944f, 0.6454972f,
    0.1394333f, 0.3415650f, 1.0801234f, 2.6457513f, 1.0801234f, 0.3415650f, 0.1394333f,
    0.0211289f, 0.0597614f, 0.2236068f, 0.9486833f, 3.0f,
    0.9486833f, 0.2236068f, 0.0597614f, 0.0211289f
};

__device__ __forceinline__ uint32_t smem_u32(const void* p) {
    uint32_t a;
    asm("{ .reg .u64 t; cvta.to.shared.u64 t, %1; cvt.u32.u64 %0, t; }" : "=r"(a) : "l"(p));
    return a;
}

// ---------------------------------------------------------------------------
// Single fused kernel. Blocks [0, EDGE_BLOCKS) compute edge features + index
// arrays; remaining blocks do the embedding gather. Feature rows staged in
// shared memory (conflict-free, row stride 57) and drained with ONE bulk
// async store (TMA path) per block instead of a per-thread LDS/STG loop.
// ---------------------------------------------------------------------------
__global__ __launch_bounds__(EPB) void fused_kernel(
    const float* __restrict__ pos,
    const float* __restrict__ alpha,
    const int*   __restrict__ an,
    const float* __restrict__ table,
    float* __restrict__ out)
{
    // ---------------- embedding-gather blocks ----------------
    if (blockIdx.x >= EDGE_BLOCKS) {
        const int i = (blockIdx.x - EDGE_BLOCKS) * EPB + threadIdx.x; // < EMB_F4
        const int n = i >> 5;            // 32 float4 per node (HS=128)
        const int h = i & 31;
        const int a = __ldg(&an[n]);
        const float4 v = ((const float4*)table)[a * 32 + h];
        ((float4*)(out + OFF_EMB))[i] = v;
        return;
    }

    // ---------------- edge blocks ----------------
    __shared__ __align__(16) float sfeat[EPB * FEAT_W];   // 43776 B

    const int e0 = blockIdx.x * EPB;
    const int e  = e0 + threadIdx.x;

    // Decode edge -> (b, src s, dst d)
    const int b = e / EDGES_PER_MOL;
    const int t = e - b * EDGES_PER_MOL;
    const int s = t / (M_ATOMS - 1);
    const int k = t - s * (M_ATOMS - 1);
    const int d = k + (k >= s ? 1 : 0);
    const int dst = b * M_ATOMS + d;
    const int src = b * M_ATOMS + s;

    // Edge vector (pos: 147 KB, L1/L2-resident)
    const float ex = pos[dst * 3 + 0] - pos[src * 3 + 0];
    const float ey = pos[dst * 3 + 1] - pos[src * 3 + 1];
    const float ez = pos[dst * 3 + 2] - pos[src * 3 + 2];
    float r = sqrtf(ex * ex + ey * ey + ez * ez);
    r = fmaxf(r, 1e-6f);
    const float inv_r = 1.0f / r;

    // --- RBF: exponential Bernstein x bump cutoff ---
    const float a  = 0.5f * alpha[0];
    const float xx = -a * r;
    const float lp = __logf(-expm1f(xx));        // log(1 - e^{xx})
    const float rc  = r * (1.0f / 15.0f);
    const float den = fmaxf((1.0f - rc) * (1.0f + rc), 1e-9f);
    const float fcut = (rc < 1.0f) ? __expf(-rc * rc / den) : 0.0f;

    float* row = &sfeat[threadIdx.x * FEAT_W];
    #pragma unroll
    for (int v = 0; v < K_RBF; v++) {
        float logb = c_logbinom[v] + (float)(K_RBF - 1 - v) * xx + (float)v * lp;
        row[v] = fcut * __expf(logb);
    }

    // --- Real spherical harmonics (component-normalized, z-up), LMAX=4 ---
    const float x = ex * inv_r, y = ey * inv_r, z = ez * inv_r;

    const float C1 = x,               S1 = y;
    const float C2 = C1 * x - S1 * y, S2 = S1 * x + C1 * y;
    const float C3 = C2 * x - S2 * y, S3 = S2 * x + C2 * y;
    const float C4 = C3 * x - S3 * y, S4 = S3 * x + C3 * y;

    const float Q00 = 1.0f;
    const float Q10 = z;
    const float Q20 = (3.0f * z * Q10 - 1.0f * Q00) * 0.5f;
    const float Q30 = (5.0f * z * Q20 - 2.0f * Q10) * (1.0f / 3.0f);
    const float Q40 = (7.0f * z * Q30 - 3.0f * Q20) * 0.25f;
    const float Q11 = 1.0f;
    const float Q21 = 3.0f * z;
    const float Q31 = (5.0f * z * Q21 - 3.0f * Q11) * 0.5f;
    const float Q41 = (7.0f * z * Q31 - 4.0f * Q21) * (1.0f / 3.0f);
    const float Q22 = 3.0f;
    const float Q32 = 5.0f * z * Q22;
    const float Q42 = (7.0f * z * Q32 - 5.0f * Q22) * 0.5f;
    const float Q33 = 15.0f;
    const float Q43 = 7.0f * z * Q33;
    const float Q44 = 105.0f;

    float* sh = row + K_RBF;
    sh[0]  = c_shcoef[0];
    sh[1]  = c_shcoef[1]  * Q11 * S1;
    sh[2]  = c_shcoef[2]  * Q10;
    sh[3]  = c_shcoef[3]  * Q11 * C1;
    sh[4]  = c_shcoef[4]  * Q22 * S2;
    sh[5]  = c_shcoef[5]  * Q21 * S1;
    sh[6]  = c_shcoef[6]  * Q20;
    sh[7]  = c_shcoef[7]  * Q21 * C1;
    sh[8]  = c_shcoef[8]  * Q22 * C2;
    sh[9]  = c_shcoef[9]  * Q33 * S3;
    sh[10] = c_shcoef[10] * Q32 * S2;
    sh[11] = c_shcoef[11] * Q31 * S1;
    sh[12] = c_shcoef[12] * Q30;
    sh[13] = c_shcoef[13] * Q31 * C1;
    sh[14] = c_shcoef[14] * Q32 * C2;
    sh[15] = c_shcoef[15] * Q33 * C3;
    sh[16] = c_shcoef[16] * Q44 * S4;
    sh[17] = c_shcoef[17] * Q43 * S3;
    sh[18] = c_shcoef[18] * Q42 * S2;
    sh[19] = c_shcoef[19] * Q41 * S1;
    sh[20] = c_shcoef[20] * Q40;
    sh[21] = c_shcoef[21] * Q41 * C1;
    sh[22] = c_shcoef[22] * Q42 * C2;
    sh[23] = c_shcoef[23] * Q43 * C3;
    sh[24] = c_shcoef[24] * Q44 * C4;

    // --- edge_index + transpose_index (coalesced scalar stores) ---
    out[OFF_EI + e]           = (float)dst;
    out[OFF_EI + E_TOTAL + e] = (float)src;
    const int tr = b * EDGES_PER_MOL + d * (M_ATOMS - 1) + s - (d < s ? 1 : 0);
    out[OFF_TR + e] = (float)tr;

    __syncthreads();

    // --- Drain: one bulk async store (SMEM -> GMEM) for the whole tile ---
    if (threadIdx.x == 0) {
        asm volatile("fence.proxy.async.shared::cta;" ::: "memory");
        const uint32_t src_s = smem_u32(sfeat);
        void* dst_g = (void*)(out + (size_t)e0 * FEAT_W);   // 43776B tiles, 16B aligned
        asm volatile(
            "cp.async.bulk.global.shared::cta.bulk_group [%0], [%1], %2;"
            :: "l"(dst_g), "r"(src_s), "n"(EPB * FEAT_W * 4) : "memory");
        asm volatile("cp.async.bulk.commit_group;" ::: "memory");
        asm volatile("cp.async.bulk.wait_group 0;" ::: "memory");
    }
}

extern "C" void kernel_launch(void* const* d_in, const int* in_sizes, int n_in,
                              void* d_out, int out_size) {
    const float* pos   = (const float*)d_in[0];
    const int*   an    = (const int*)d_in[1];
    const float* table = (const float*)d_in[2];
    const float* alpha = (const float*)d_in[3];
    float* out = (float*)d_out;

    fused_kernel<<<EDGE_BLOCKS + EMB_BLOCKS, EPB>>>(pos, alpha, an, table, out);
}

// round 7
// speedup vs baseline: 1.9512x; 1.0418x over previous
#include <cuda_runtime.h>
#include <cuda_bf16.h>
#include <cstdint>

// Problem constants
#define B_MOLS 256
#define M_ATOMS 48
#define EDGES_PER_MOL (M_ATOMS * (M_ATOMS - 1))   // 2256
#define E_TOTAL (B_MOLS * EDGES_PER_MOL)          // 577536
#define N_ATOMS (B_MOLS * M_ATOMS)                // 12288
#define K_RBF 32
#define HS 128
#define NSH 25
#define FEAT_W 57                                  // 32 RBF + 25 SH

// Output layout (flattened reference tuple, float32)
#define OFF_FEAT 0ULL
#define OFF_EMB  ((size_t)E_TOTAL * FEAT_W)                    // 32919552
#define OFF_EI   (OFF_EMB + (size_t)N_ATOMS * HS)              // 34492416
#define OFF_TR   (OFF_EI + 2ULL * E_TOTAL)                     // 35647488

#define EPB 128
#define EDGE_BLOCKS (E_TOTAL / EPB)                            // 4512
#define EMB_F4 (N_ATOMS * HS / 4)                              // 393216
#define EMB_BLOCKS (EMB_F4 / EPB)                              // 3072

// ln C(31, v), v = 0..31
__constant__ float c_logbinom[K_RBF] = {
    0.0f,        3.4339872f,  6.1420374f,  8.4107209f,
    10.3566311f, 12.0430300f, 13.5093671f, 14.7823328f,
    15.8809451f, 16.8192147f, 17.6076721f, 18.2542992f,
    18.7651249f, 19.1446145f, 19.3959290f, 19.5210921f,
    19.5210921f, 19.3959290f, 19.1446145f, 18.7651249f,
    18.2542992f, 17.6076721f, 16.8192147f, 15.8809451f,
    14.7823328f, 13.5093671f, 12.0430300f, 10.3566311f,
    8.4107209f,  6.1420374f,  3.4339872f,  0.0f
};

// sqrt((2l+1)(l-|m|)!/(l+|m|)!) * (sqrt(2) if m!=0), j = l*l+l+m
__constant__ float c_shcoef[NSH] = {
    1.0f,
    1.7320508f, 1.7320508f, 1.7320508f,
    0.6454972f, 1.2909944f, 2.2360680f, 1.2909944f, 0.6454972f,
    0.1394333f, 0.3415650f, 1.0801234f, 2.6457513f, 1.0801234f, 0.3415650f, 0.1394333f,
    0.0211289f, 0.0597614f, 0.2236068f, 0.9486833f, 3.0f,
    0.9486833f, 0.2236068f, 0.0597614f, 0.0211289f
};

__device__ __forceinline__ uint32_t smem_u32(const void* p) {
    uint32_t a;
    asm("{ .reg .u64 t; cvta.to.shared.u64 t, %1; cvt.u32.u64 %0, t; }" : "=r"(a) : "l"(p));
    return a;
}

// ---------------------------------------------------------------------------
// Single fused kernel. Blocks [0, EDGE_BLOCKS) compute edge features + index
// arrays; remaining blocks do the embedding gather. Feature rows staged in
// shared memory (conflict-free, row stride 57) and drained with ONE bulk
// async store per block; we only wait for the smem-READ side so the global
// write completes in the background while the CTA retires.
// ---------------------------------------------------------------------------
__global__ __launch_bounds__(EPB) void fused_kernel(
    const float* __restrict__ pos,
    const float* __restrict__ alpha,
    const int*   __restrict__ an,
    const float* __restrict__ table,
    float* __restrict__ out)
{
    // ---------------- embedding-gather blocks ----------------
    if (blockIdx.x >= EDGE_BLOCKS) {
        const int i = (blockIdx.x - EDGE_BLOCKS) * EPB + threadIdx.x; // < EMB_F4
        const int n = i >> 5;            // 32 float4 per node (HS=128)
        const int h = i & 31;
        const int a = __ldg(&an[n]);
        const float4 v = ((const float4*)table)[a * 32 + h];
        ((float4*)(out + OFF_EMB))[i] = v;
        return;
    }

    // ---------------- edge blocks ----------------
    __shared__ __align__(16) float sfeat[EPB * FEAT_W];   // 29184 B -> 7 CTAs/SM

    const int e0 = blockIdx.x * EPB;
    const int e  = e0 + threadIdx.x;

    // Decode edge -> (b, src s, dst d)
    const int b = e / EDGES_PER_MOL;
    const int t = e - b * EDGES_PER_MOL;
    const int s = t / (M_ATOMS - 1);
    const int k = t - s * (M_ATOMS - 1);
    const int d = k + (k >= s ? 1 : 0);
    const int dst = b * M_ATOMS + d;
    const int src = b * M_ATOMS + s;

    // Edge vector (pos: 147 KB, L1/L2-resident)
    const float ex = pos[dst * 3 + 0] - pos[src * 3 + 0];
    const float ey = pos[dst * 3 + 1] - pos[src * 3 + 1];
    const float ez = pos[dst * 3 + 2] - pos[src * 3 + 2];
    float r = sqrtf(ex * ex + ey * ey + ez * ez);
    r = fmaxf(r, 1e-6f);
    const float inv_r = 1.0f / r;

    // --- RBF: exponential Bernstein x bump cutoff ---
    const float a  = 0.5f * alpha[0];
    const float xx = -a * r;
    const float lp = __logf(-expm1f(xx));        // log(1 - e^{xx})
    const float rc  = r * (1.0f / 15.0f);
    const float den = fmaxf((1.0f - rc) * (1.0f + rc), 1e-9f);
    const float fcut = (rc < 1.0f) ? __expf(-rc * rc / den) : 0.0f;

    float* row = &sfeat[threadIdx.x * FEAT_W];
    #pragma unroll
    for (int v = 0; v < K_RBF; v++) {
        float logb = c_logbinom[v] + (float)(K_RBF - 1 - v) * xx + (float)v * lp;
        row[v] = fcut * __expf(logb);
    }

    // --- Real spherical harmonics (component-normalized, z-up), LMAX=4 ---
    const float x = ex * inv_r, y = ey * inv_r, z = ez * inv_r;

    const float C1 = x,               S1 = y;
    const float C2 = C1 * x - S1 * y, S2 = S1 * x + C1 * y;
    const float C3 = C2 * x - S2 * y, S3 = S2 * x + C2 * y;
    const float C4 = C3 * x - S3 * y, S4 = S3 * x + C3 * y;

    const float Q00 = 1.0f;
    const float Q10 = z;
    const float Q20 = (3.0f * z * Q10 - 1.0f * Q00) * 0.5f;
    const float Q30 = (5.0f * z * Q20 - 2.0f * Q10) * (1.0f / 3.0f);
    const float Q40 = (7.0f * z * Q30 - 3.0f * Q20) * 0.25f;
    const float Q11 = 1.0f;
    const float Q21 = 3.0f * z;
    const float Q31 = (5.0f * z * Q21 - 3.0f * Q11) * 0.5f;
    const float Q41 = (7.0f * z * Q31 - 4.0f * Q21) * (1.0f / 3.0f);
    const float Q22 = 3.0f;
    const float Q32 = 5.0f * z * Q22;
    const float Q42 = (7.0f * z * Q32 - 5.0f * Q22) * 0.5f;
    const float Q33 = 15.0f;
    const float Q43 = 7.0f * z * Q33;
    const float Q44 = 105.0f;

    float* sh = row + K_RBF;
    sh[0]  = c_shcoef[0];
    sh[1]  = c_shcoef[1]  * Q11 * S1;
    sh[2]  = c_shcoef[2]  * Q10;
    sh[3]  = c_shcoef[3]  * Q11 * C1;
    sh[4]  = c_shcoef[4]  * Q22 * S2;
    sh[5]  = c_shcoef[5]  * Q21 * S1;
    sh[6]  = c_shcoef[6]  * Q20;
    sh[7]  = c_shcoef[7]  * Q21 * C1;
    sh[8]  = c_shcoef[8]  * Q22 * C2;
    sh[9]  = c_shcoef[9]  * Q33 * S3;
    sh[10] = c_shcoef[10] * Q32 * S2;
    sh[11] = c_shcoef[11] * Q31 * S1;
    sh[12] = c_shcoef[12] * Q30;
    sh[13] = c_shcoef[13] * Q31 * C1;
    sh[14] = c_shcoef[14] * Q32 * C2;
    sh[15] = c_shcoef[15] * Q33 * C3;
    sh[16] = c_shcoef[16] * Q44 * S4;
    sh[17] = c_shcoef[17] * Q43 * S3;
    sh[18] = c_shcoef[18] * Q42 * S2;
    sh[19] = c_shcoef[19] * Q41 * S1;
    sh[20] = c_shcoef[20] * Q40;
    sh[21] = c_shcoef[21] * Q41 * C1;
    sh[22] = c_shcoef[22] * Q42 * C2;
    sh[23] = c_shcoef[23] * Q43 * C3;
    sh[24] = c_shcoef[24] * Q44 * C4;

    // --- edge_index + transpose_index (coalesced scalar stores) ---
    out[OFF_EI + e]           = (float)dst;
    out[OFF_EI + E_TOTAL + e] = (float)src;
    const int tr = b * EDGES_PER_MOL + d * (M_ATOMS - 1) + s - (d < s ? 1 : 0);
    out[OFF_TR + e] = (float)tr;

    __syncthreads();

    // --- Drain: one bulk async store (SMEM -> GMEM); wait on READ only ---
    if (threadIdx.x == 0) {
        asm volatile("fence.proxy.async.shared::cta;" ::: "memory");
        const uint32_t src_s = smem_u32(sfeat);
        void* dst_g = (void*)(out + (size_t)e0 * FEAT_W);   // 29184B tiles, 16B aligned
        asm volatile(
            "cp.async.bulk.global.shared::cta.bulk_group [%0], [%1], %2;"
            :: "l"(dst_g), "r"(src_s), "n"(EPB * FEAT_W * 4) : "memory");
        asm volatile("cp.async.bulk.commit_group;" ::: "memory");
        asm volatile("cp.async.bulk.wait_group.read 0;" ::: "memory");
    }
}

extern "C" void kernel_launch(void* const* d_in, const int* in_sizes, int n_in,
                              void* d_out, int out_size) {
    const float* pos   = (const float*)d_in[0];
    const int*   an    = (const int*)d_in[1];
    const float* table = (const float*)d_in[2];
    const float* alpha = (const float*)d_in[3];
    float* out = (float*)d_out;

    fused_kernel<<<EDGE_BLOCKS + EMB_BLOCKS, EPB>>>(pos, alpha, an, table, out);
}

// round 8
// speedup vs baseline: 1.9811x; 1.0153x over previous
#include <cuda_runtime.h>
#include <cuda_bf16.h>
#include <cstdint>

// Problem constants
#define B_MOLS 256
#define M_ATOMS 48
#define EDGES_PER_MOL (M_ATOMS * (M_ATOMS - 1))   // 2256
#define E_TOTAL (B_MOLS * EDGES_PER_MOL)          // 577536
#define N_ATOMS (B_MOLS * M_ATOMS)                // 12288
#define K_RBF 32
#define HS 128
#define NSH 25
#define FEAT_W 57                                  // 32 RBF + 25 SH

// Output layout (flattened reference tuple, float32)
#define OFF_FEAT 0ULL
#define OFF_EMB  ((size_t)E_TOTAL * FEAT_W)                    // 32919552
#define OFF_EI   (OFF_EMB + (size_t)N_ATOMS * HS)              // 34492416
#define OFF_TR   (OFF_EI + 2ULL * E_TOTAL)                     // 35647488

#define EPB 128
#define EDGE_BLOCKS (E_TOTAL / EPB)                            // 4512
#define EMB_F4 (N_ATOMS * HS / 4)                              // 393216
#define EMB_BLOCKS (EMB_F4 / EPB)                              // 3072

#define LOG2E 1.4426950408889634f

// log2 C(31, v), v = 0..31  (= ln C(31,v) * log2e)
__constant__ float c_lb2[K_RBF] = {
    0.0f,       4.954196f,  8.861087f, 12.134094f,
    14.941449f, 17.374408f, 19.489885f, 21.326386f,
    22.911349f, 24.264986f, 25.402490f, 26.335418f,
    27.072384f, 27.620101f, 27.982671f, 28.163244f,
    28.163244f, 27.982671f, 27.620101f, 27.072384f,
    26.335418f, 25.402490f, 24.264986f, 22.911349f,
    21.326386f, 19.489885f, 17.374408f, 14.941449f,
    12.134094f, 8.861087f,  4.954196f,  0.0f
};

// sqrt((2l+1)(l-|m|)!/(l+|m|)!) * (sqrt(2) if m!=0), j = l*l+l+m
__constant__ float c_shcoef[NSH] = {
    1.0f,
    1.7320508f, 1.7320508f, 1.7320508f,
    0.6454972f, 1.2909944f, 2.2360680f, 1.2909944f, 0.6454972f,
    0.1394333f, 0.3415650f, 1.0801234f, 2.6457513f, 1.0801234f, 0.3415650f, 0.1394333f,
    0.0211289f, 0.0597614f, 0.2236068f, 0.9486833f, 3.0f,
    0.9486833f, 0.2236068f, 0.0597614f, 0.0211289f
};

__device__ __forceinline__ uint32_t smem_u32(const void* p) {
    uint32_t a;
    asm("{ .reg .u64 t; cvta.to.shared.u64 t, %1; cvt.u32.u64 %0, t; }" : "=f"(*(float*)&a) : "l"(p));
    return a;
}

__device__ __forceinline__ uint32_t smem_addr(const void* p) {
    uint32_t a;
    asm("{ .reg .u64 t; cvta.to.shared.u64 t, %1; cvt.u32.u64 %0, t; }" : "=r"(a) : "l"(p));
    return a;
}

__device__ __forceinline__ float ex2f(float x) {
    float y;
    asm("ex2.approx.ftz.f32 %0, %1;" : "=f"(y) : "f"(x));
    return y;
}

// ---------------------------------------------------------------------------
// Single fused kernel. Blocks [0, EDGE_BLOCKS) compute edge features + index
// arrays; remaining blocks do the embedding gather. Each warp owns a
// contiguous 32-row (7296 B) slice of the staging buffer and drains it with
// its OWN bulk async store after __syncwarp — no block-wide barrier, drains
// overlap other warps' compute.
// ---------------------------------------------------------------------------
__global__ __launch_bounds__(EPB) void fused_kernel(
    const float* __restrict__ pos,
    const float* __restrict__ alpha,
    const int*   __restrict__ an,
    const float* __restrict__ table,
    float* __restrict__ out)
{
    // ---------------- embedding-gather blocks ----------------
    if (blockIdx.x >= EDGE_BLOCKS) {
        const int i = (blockIdx.x - EDGE_BLOCKS) * EPB + threadIdx.x; // < EMB_F4
        const int n = i >> 5;            // 32 float4 per node (HS=128)
        const int h = i & 31;
        const int a = __ldg(&an[n]);
        const float4 v = ((const float4*)table)[a * 32 + h];
        ((float4*)(out + OFF_EMB))[i] = v;
        return;
    }

    // ---------------- edge blocks ----------------
    __shared__ __align__(16) float sfeat[EPB * FEAT_W];   // 29184 B -> 7 CTAs/SM

    const int e0 = blockIdx.x * EPB;
    const int e  = e0 + threadIdx.x;

    // Decode edge -> (b, src s, dst d)
    const int b = e / EDGES_PER_MOL;
    const int t = e - b * EDGES_PER_MOL;
    const int s = t / (M_ATOMS - 1);
    const int k = t - s * (M_ATOMS - 1);
    const int d = k + (k >= s ? 1 : 0);
    const int dst = b * M_ATOMS + d;
    const int src = b * M_ATOMS + s;

    // Edge vector (pos: 147 KB, L1/L2-resident)
    const float ex = pos[dst * 3 + 0] - pos[src * 3 + 0];
    const float ey = pos[dst * 3 + 1] - pos[src * 3 + 1];
    const float ez = pos[dst * 3 + 2] - pos[src * 3 + 2];
    float r = sqrtf(ex * ex + ey * ey + ez * ez);
    r = fmaxf(r, 1e-6f);
    const float inv_r = 1.0f / r;

    // --- RBF in log2 space ---
    // logb_v = lnC + (31-v)*xx + v*lp + ln(fcut)
    // L2_v   = lb2[v] + base + v*w2 ;  base=(31*xx+lnfcut)*log2e, w2=(lp-xx)*log2e
    const float a  = 0.5f * alpha[0];
    const float xx = -a * r;
    const float lp = __logf(-expm1f(xx));        // ln(1 - e^{xx})
    const float rc  = r * (1.0f / 15.0f);
    const float den = fmaxf((1.0f - rc) * (1.0f + rc), 1e-9f);
    const float lnfcut = (rc < 1.0f) ? (-rc * rc * __frcp_rn(den)) : -1.0e9f;
    const float base = (31.0f * xx + lnfcut) * LOG2E;
    const float w2   = (lp - xx) * LOG2E;

    float* row = &sfeat[threadIdx.x * FEAT_W];
    #pragma unroll
    for (int v = 0; v < K_RBF; v++) {
        row[v] = ex2f(fmaf((float)v, w2, base + c_lb2[v]));
    }

    // --- Real spherical harmonics (component-normalized, z-up), LMAX=4 ---
    const float x = ex * inv_r, y = ey * inv_r, z = ez * inv_r;

    const float C1 = x,               S1 = y;
    const float C2 = C1 * x - S1 * y, S2 = S1 * x + C1 * y;
    const float C3 = C2 * x - S2 * y, S3 = S2 * x + C2 * y;
    const float C4 = C3 * x - S3 * y, S4 = S3 * x + C3 * y;

    const float Q00 = 1.0f;
    const float Q10 = z;
    const float Q20 = (3.0f * z * Q10 - 1.0f * Q00) * 0.5f;
    const float Q30 = (5.0f * z * Q20 - 2.0f * Q10) * (1.0f / 3.0f);
    const float Q40 = (7.0f * z * Q30 - 3.0f * Q20) * 0.25f;
    const float Q11 = 1.0f;
    const float Q21 = 3.0f * z;
    const float Q31 = (5.0f * z * Q21 - 3.0f * Q11) * 0.5f;
    const float Q41 = (7.0f * z * Q31 - 4.0f * Q21) * (1.0f / 3.0f);
    const float Q22 = 3.0f;
    const float Q32 = 5.0f * z * Q22;
    const float Q42 = (7.0f * z * Q32 - 5.0f * Q22) * 0.5f;
    const float Q33 = 15.0f;
    const float Q43 = 7.0f * z * Q33;
    const float Q44 = 105.0f;

    float* sh = row + K_RBF;
    sh[0]  = c_shcoef[0];
    sh[1]  = c_shcoef[1]  * Q11 * S1;
    sh[2]  = c_shcoef[2]  * Q10;
    sh[3]  = c_shcoef[3]  * Q11 * C1;
    sh[4]  = c_shcoef[4]  * Q22 * S2;
    sh[5]  = c_shcoef[5]  * Q21 * S1;
    sh[6]  = c_shcoef[6]  * Q20;
    sh[7]  = c_shcoef[7]  * Q21 * C1;
    sh[8]  = c_shcoef[8]  * Q22 * C2;
    sh[9]  = c_shcoef[9]  * Q33 * S3;
    sh[10] = c_shcoef[10] * Q32 * S2;
    sh[11] = c_shcoef[11] * Q31 * S1;
    sh[12] = c_shcoef[12] * Q30;
    sh[13] = c_shcoef[13] * Q31 * C1;
    sh[14] = c_shcoef[14] * Q32 * C2;
    sh[15] = c_shcoef[15] * Q33 * C3;
    sh[16] = c_shcoef[16] * Q44 * S4;
    sh[17] = c_shcoef[17] * Q43 * S3;
    sh[18] = c_shcoef[18] * Q42 * S2;
    sh[19] = c_shcoef[19] * Q41 * S1;
    sh[20] = c_shcoef[20] * Q40;
    sh[21] = c_shcoef[21] * Q41 * C1;
    sh[22] = c_shcoef[22] * Q42 * C2;
    sh[23] = c_shcoef[23] * Q43 * C3;
    sh[24] = c_shcoef[24] * Q44 * C4;

    // --- edge_index + transpose_index (coalesced scalar stores) ---
    out[OFF_EI + e]           = (float)dst;
    out[OFF_EI + E_TOTAL + e] = (float)src;
    const int tr = b * EDGES_PER_MOL + d * (M_ATOMS - 1) + s - (d < s ? 1 : 0);
    out[OFF_TR + e] = (float)tr;

    // --- Per-warp drain: each warp bulk-stores its own contiguous slice ---
    __syncwarp();
    const int w = threadIdx.x >> 5;
    if ((threadIdx.x & 31) == 0) {
        asm volatile("fence.proxy.async.shared::cta;" ::: "memory");
        const uint32_t src_s = smem_addr(&sfeat[w * 32 * FEAT_W]);   // 7296B slice
        void* dst_g = (void*)(out + (size_t)(e0 + w * 32) * FEAT_W); // 16B aligned
        asm volatile(
            "cp.async.bulk.global.shared::cta.bulk_group [%0], [%1], %2;"
            :: "l"(dst_g), "r"(src_s), "n"(32 * FEAT_W * 4) : "memory");
        asm volatile("cp.async.bulk.commit_group;" ::: "memory");
        asm volatile("cp.async.bulk.wait_group.read 0;" ::: "memory");
    }
}

extern "C" void kernel_launch(void* const* d_in, const int* in_sizes, int n_in,
                              void* d_out, int out_size) {
    const float* pos   = (const float*)d_in[0];
    const int*   an    = (const int*)d_in[1];
    const float* table = (const float*)d_in[2];
    const float* alpha = (const float*)d_in[3];
    float* out = (float*)d_out;

    fused_kernel<<<EDGE_BLOCKS + EMB_BLOCKS, EPB>>>(pos, alpha, an, table, out);
}